// round 1
// baseline (speedup 1.0000x reference)
#include <cuda_runtime.h>
#include <cstdint>

#define HH 192
#define WW 192
#define BB 4
#define HWW (HH*WW)

// ---------------- scratch buffers (device globals; no allocation) ----------
__device__ float g_c1a[BB*64*HWW];
__device__ float g_c1b[BB*64*HWW];
__device__ float g_c2a[BB*128*HWW];
__device__ float g_c2b[BB*128*HWW];
__device__ float g_redir[BB*32*HWW];
__device__ float g_corr[BB*441*HWW];

__device__ __forceinline__ float lrelu(float x) { return x >= 0.f ? x : 0.1f * x; }

// ---------------- 3x3 conv + bias + leaky relu -----------------------------
// Block 16x16 threads, each thread computes a 2x2 spatial patch for 4 output
// channels. Output tile per block: 32x32 px x 4 co. Loop input channels in
// chunks of 8 staged through shared memory.
template<int CIN, int COUT>
__global__ __launch_bounds__(256)
void conv3x3_lrelu(const float* __restrict__ in, const float* __restrict__ wgt,
                   const float* __restrict__ bias, float* __restrict__ out)
{
    const int bx = blockIdx.x;            // W/32
    const int by = blockIdx.y;            // H/32
    const int bz = blockIdx.z;            // b * (COUT/4) + cog
    const int b   = bz / (COUT/4);
    const int co0 = (bz % (COUT/4)) * 4;
    const int tx = threadIdx.x, ty = threadIdx.y;
    const int tid = ty*16 + tx;
    const int x0 = bx*32, y0 = by*32;

    __shared__ float s_in[8][34][35];
    __shared__ float s_w[4][8][9];

    float acc[4][2][2];
#pragma unroll
    for (int o = 0; o < 4; o++)
#pragma unroll
        for (int py = 0; py < 2; py++)
#pragma unroll
            for (int px = 0; px < 2; px++) acc[o][py][px] = 0.f;

    for (int c0 = 0; c0 < CIN; c0 += 8) {
        // stage input tile (8 x 34 x 34 with halo)
        for (int i = tid; i < 8*34*34; i += 256) {
            int c  = i / (34*34);
            int r  = i % (34*34);
            int ly = r / 34, lx = r % 34;
            int gy = y0 + ly - 1, gx = x0 + lx - 1;
            float v = 0.f;
            if (gy >= 0 && gy < HH && gx >= 0 && gx < WW)
                v = in[(((b*CIN) + c0 + c)*HH + gy)*WW + gx];
            s_in[c][ly][lx] = v;
        }
        // stage weights (4 co x 8 ci x 9)
        for (int i = tid; i < 4*8*9; i += 256) {
            int o = i / 72;
            int r = i % 72;
            int c = r / 9, k = r % 9;
            s_w[o][c][k] = wgt[((co0 + o)*CIN + c0 + c)*9 + k];
        }
        __syncthreads();

#pragma unroll
        for (int c = 0; c < 8; c++) {
#pragma unroll
            for (int ky = 0; ky < 3; ky++) {
#pragma unroll
                for (int kx = 0; kx < 3; kx++) {
                    const float w0 = s_w[0][c][ky*3+kx];
                    const float w1 = s_w[1][c][ky*3+kx];
                    const float w2 = s_w[2][c][ky*3+kx];
                    const float w3 = s_w[3][c][ky*3+kx];
#pragma unroll
                    for (int py = 0; py < 2; py++) {
#pragma unroll
                        for (int px = 0; px < 2; px++) {
                            const float v = s_in[c][ty*2+py+ky][tx*2+px+kx];
                            acc[0][py][px] += v * w0;
                            acc[1][py][px] += v * w1;
                            acc[2][py][px] += v * w2;
                            acc[3][py][px] += v * w3;
                        }
                    }
                }
            }
        }
        __syncthreads();
    }

#pragma unroll
    for (int o = 0; o < 4; o++) {
        const float bv = bias[co0 + o];
#pragma unroll
        for (int py = 0; py < 2; py++) {
#pragma unroll
            for (int px = 0; px < 2; px++) {
                const int y = y0 + ty*2 + py;
                const int x = x0 + tx*2 + px;
                out[(((b*COUT) + co0 + o)*HH + y)*WW + x] = lrelu(acc[o][py][px] + bv);
            }
        }
    }
}

// ---------------- 1x1 redir conv + lrelu -----------------------------------
// 128 -> 32 channels. Block handles 64 pixels; inputs staged in smem.
__global__ __launch_bounds__(256)
void redir_conv(const float* __restrict__ in, const float* __restrict__ wgt,
                const float* __restrict__ bias, float* __restrict__ out)
{
    const int b  = blockIdx.y;
    const int p0 = blockIdx.x * 64;
    const int tid = threadIdx.x;

    __shared__ float s[128*64];
    for (int i = tid; i < 128*64; i += 256) {
        int c = i / 64, p = i % 64;
        s[c*64 + p] = in[(b*128 + c)*HWW + p0 + p];
    }
    __syncthreads();

    for (int oi = tid; oi < 32*64; oi += 256) {
        const int co = oi / 64;
        const int p  = oi % 64;
        float sum = bias[co];
#pragma unroll 16
        for (int c = 0; c < 128; c++)
            sum += s[c*64 + p] * __ldg(&wgt[co*128 + c]);
        out[(b*32 + co)*HWW + p0 + p] = lrelu(sum);
    }
}

// ---------------- correlation (patch 21, dilation 2) + lrelu ----------------
// Block = one (b, y, 32-pixel x-tile). A vectors (128ch x 32px) in smem,
// loop dy: load the shifted B row segment (128ch x 72px) and compute all 21 dx.
__global__ __launch_bounds__(256)
void corr_kernel(const float* __restrict__ A, const float* __restrict__ Bm,
                 float* __restrict__ out)
{
    extern __shared__ float smem[];
    float* sA = smem;           // [128][32]
    float* sB = smem + 128*32;  // [128][72]

    const int x0 = blockIdx.x * 32;
    const int y  = blockIdx.y;
    const int b  = blockIdx.z;
    const int tid = threadIdx.x;

    // load A[c][px]
    for (int i = tid; i < 128*32; i += 256) {
        int c = i / 32, px = i % 32;
        sA[c*32 + px] = A[((b*128 + c)*HH + y)*WW + x0 + px];
    }

    const float inv_c = 1.0f / 128.0f;

    for (int dy = 0; dy < 21; dy++) {
        const int ry = y + dy*2 - 20;
        __syncthreads();
        if (ry < 0 || ry >= HH) {
            // out-of-range row: correlation is exactly 0
            for (int i = tid; i < 21*32; i += 256) {
                int dx = i / 32, px = i % 32;
                out[((b*441 + dy*21 + dx)*HH + y)*WW + x0 + px] = 0.f;
            }
            continue;
        }
        // load shifted B row: u in [0,72) -> global x = x0 - 20 + u
        for (int i = tid; i < 128*72; i += 256) {
            int c = i / 72, u = i % 72;
            int gx = x0 - 20 + u;
            float v = 0.f;
            if (gx >= 0 && gx < WW)
                v = Bm[((b*128 + c)*HH + ry)*WW + gx];
            sB[c*72 + u] = v;
        }
        __syncthreads();

        for (int i = tid; i < 21*32; i += 256) {
            const int dx = i / 32;
            const int px = i % 32;
            const float* a = sA + px;
            const float* bp = sB + px + 2*dx;
            float sum = 0.f;
#pragma unroll 16
            for (int c = 0; c < 128; c++)
                sum += a[c*32] * bp[c*72];
            out[((b*441 + dy*21 + dx)*HH + y)*WW + x0 + px] = lrelu(sum * inv_c);
        }
    }
}

// ---------------- final 3x3 conv over concat(redir(32), corr(441)) ----------
// 2 output channels, no bias, no activation. Block = 16x16 px, chunked smem.
__global__ __launch_bounds__(256)
void final_conv(const float* __restrict__ redir, const float* __restrict__ corr,
                const float* __restrict__ wgt, float* __restrict__ out)
{
    const int x0 = blockIdx.x * 16;
    const int y0 = blockIdx.y * 16;
    const int b  = blockIdx.z;
    const int tx = threadIdx.x, ty = threadIdx.y;
    const int tid = ty*16 + tx;

    __shared__ float s[8][18][19];
    __shared__ float sw[2][8][9];

    float a0 = 0.f, a1 = 0.f;

    for (int c0 = 0; c0 < 473; c0 += 8) {
        const int cn = (473 - c0) < 8 ? (473 - c0) : 8;
        for (int i = tid; i < cn*18*18; i += 256) {
            int c  = i / (18*18);
            int r  = i % (18*18);
            int ly = r / 18, lx = r % 18;
            int gy = y0 + ly - 1, gx = x0 + lx - 1;
            int cg = c0 + c;
            float v = 0.f;
            if (gy >= 0 && gy < HH && gx >= 0 && gx < WW) {
                if (cg < 32)
                    v = redir[((b*32 + cg)*HH + gy)*WW + gx];
                else
                    v = corr[((b*441 + (cg - 32))*HH + gy)*WW + gx];
            }
            s[c][ly][lx] = v;
        }
        for (int i = tid; i < 2*cn*9; i += 256) {
            int o = i / (cn*9);
            int r = i % (cn*9);
            int c = r / 9, k = r % 9;
            sw[o][c][k] = wgt[(o*473 + c0 + c)*9 + k];
        }
        __syncthreads();

        for (int c = 0; c < cn; c++) {
#pragma unroll
            for (int ky = 0; ky < 3; ky++) {
#pragma unroll
                for (int kx = 0; kx < 3; kx++) {
                    const float v = s[c][ty+ky][tx+kx];
                    a0 += v * sw[0][c][ky*3+kx];
                    a1 += v * sw[1][c][ky*3+kx];
                }
            }
        }
        __syncthreads();
    }

    const int y = y0 + ty, x = x0 + tx;
    out[((b*2 + 0)*HH + y)*WW + x] = a0;
    out[((b*2 + 1)*HH + y)*WW + x] = a1;
}

// ---------------- launch -----------------------------------------------------
extern "C" void kernel_launch(void* const* d_in, const int* in_sizes, int n_in,
                              void* d_out, int out_size)
{
    const float* pred    = (const float*)d_in[0];
    const float* ref     = (const float*)d_in[1];
    const float* conv1_w = (const float*)d_in[2];
    const float* conv1_b = (const float*)d_in[3];
    const float* conv2_w = (const float*)d_in[4];
    const float* conv2_b = (const float*)d_in[5];
    const float* redir_w = (const float*)d_in[6];
    const float* redir_b = (const float*)d_in[7];
    const float* pred_w  = (const float*)d_in[8];
    float* out = (float*)d_out;

    float *c1a, *c1b, *c2a, *c2b, *rdr, *cor;
    cudaGetSymbolAddress((void**)&c1a, g_c1a);
    cudaGetSymbolAddress((void**)&c1b, g_c1b);
    cudaGetSymbolAddress((void**)&c2a, g_c2a);
    cudaGetSymbolAddress((void**)&c2b, g_c2b);
    cudaGetSymbolAddress((void**)&rdr, g_redir);
    cudaGetSymbolAddress((void**)&cor, g_corr);

    // conv1 (64->64) on pred and ref
    {
        dim3 grid(WW/32, HH/32, BB * (64/4));
        dim3 blk(16, 16);
        conv3x3_lrelu<64,64><<<grid, blk>>>(pred, conv1_w, conv1_b, c1a);
        conv3x3_lrelu<64,64><<<grid, blk>>>(ref,  conv1_w, conv1_b, c1b);
    }
    // conv2 (64->128)
    {
        dim3 grid(WW/32, HH/32, BB * (128/4));
        dim3 blk(16, 16);
        conv3x3_lrelu<64,128><<<grid, blk>>>(c1a, conv2_w, conv2_b, c2a);
        conv3x3_lrelu<64,128><<<grid, blk>>>(c1b, conv2_w, conv2_b, c2b);
    }
    // redir 1x1 (128->32)
    {
        dim3 grid(HWW/64, BB);
        redir_conv<<<grid, 256>>>(c2a, redir_w, redir_b, rdr);
    }
    // correlation
    {
        const int smem_bytes = (128*32 + 128*72) * (int)sizeof(float); // 53248
        cudaFuncSetAttribute(corr_kernel, cudaFuncAttributeMaxDynamicSharedMemorySize, smem_bytes);
        dim3 grid(WW/32, HH, BB);
        corr_kernel<<<grid, 256, smem_bytes>>>(c2a, c2b, cor);
    }
    // final conv (473->2)
    {
        dim3 grid(WW/16, HH/16, BB);
        dim3 blk(16, 16);
        final_conv<<<grid, blk>>>(rdr, cor, pred_w, out);
    }
}

// round 2
// speedup vs baseline: 1.6891x; 1.6891x over previous
#include <cuda_runtime.h>
#include <cstdint>

#define HH 192
#define WW 192
#define BB 4
#define HWW (HH*WW)

// ---------------- scratch buffers (device globals; no allocation) ----------
__device__ float g_c1a[BB*64*HWW];
__device__ float g_c1b[BB*64*HWW];
__device__ float g_c2a[BB*128*HWW];
__device__ float g_c2b[BB*128*HWW];
__device__ float g_redir[BB*32*HWW];
__device__ float g_corr[BB*441*HWW];

__device__ __forceinline__ float lrelu(float x) { return x >= 0.f ? x : 0.1f * x; }

// ---------------- 3x3 conv + bias + leaky relu (v2) -------------------------
// Block 16x16 threads. Output tile: 32x32 px x 8 output channels.
// Per thread: 2x2 pixels x 8 co = 32 accumulators.
// Staging geometry (div/mod) precomputed ONCE into registers.
template<int CIN, int COUT>
__global__ __launch_bounds__(256)
void conv3x3_v2(const float* __restrict__ in, const float* __restrict__ wgt,
                const float* __restrict__ bias, float* __restrict__ out)
{
    const int x0 = blockIdx.x * 32;
    const int y0 = blockIdx.y * 32;
    const int bz = blockIdx.z;
    const int b   = bz / (COUT/8);
    const int co0 = (bz % (COUT/8)) * 8;
    const int tx = threadIdx.x, ty = threadIdx.y;
    const int tid = ty*16 + tx;

    __shared__ float s_in[8][34][36];     // [ci][row][col] col0 <-> gx = x0-1
    __shared__ float s_w[8][9][8];        // [ci][k][co]

    // --- precompute input staging slots (1156 positions, <=5 per thread) ---
    int  soff[5];  int goff[5];
    bool inb[5];   bool wr[5];
#pragma unroll
    for (int k = 0; k < 5; k++) {
        int i = tid + k*256;
        bool ok = (i < 34*34);
        int ii = ok ? i : 0;
        int ly = ii / 34, lx = ii % 34;
        int gy = y0 + ly - 1, gx = x0 + lx - 1;
        bool v = ok && (gy >= 0) && (gy < HH) && (gx >= 0) && (gx < WW);
        soff[k] = ly*36 + lx;
        goff[k] = v ? ((b*CIN)*HH + gy)*WW + gx : 0;
        inb[k]  = v;
        wr[k]   = ok;
    }
    // --- precompute weight staging slots (576 elements, <=3 per thread) ---
    int wsrc[3]; bool wok[3];
#pragma unroll
    for (int k = 0; k < 3; k++) {
        int i = tid + k*256;
        bool ok = (i < 576);
        int ii = ok ? i : 0;
        int c = ii / 72, r = ii % 72;
        int kk = r / 8, o = r % 8;
        wsrc[k] = ((co0 + o)*CIN + c)*9 + kk;   // + c0*9 later
        wok[k]  = ok;
    }

    float acc[8][2][2];
#pragma unroll
    for (int o = 0; o < 8; o++)
#pragma unroll
        for (int py = 0; py < 2; py++)
#pragma unroll
            for (int px = 0; px < 2; px++) acc[o][py][px] = 0.f;

    for (int c0 = 0; c0 < CIN; c0 += 8) {
        __syncthreads();
        // stage inputs: 8 channels per slot, stride HWW
#pragma unroll
        for (int k = 0; k < 5; k++) {
            if (wr[k]) {
                const float* p = in + goff[k] + c0*HWW;
                float* s = &s_in[0][0][0] + soff[k];
                if (inb[k]) {
#pragma unroll
                    for (int c = 0; c < 8; c++) s[c*(34*36)] = p[c*HWW];
                } else {
#pragma unroll
                    for (int c = 0; c < 8; c++) s[c*(34*36)] = 0.f;
                }
            }
        }
        // stage weights
#pragma unroll
        for (int k = 0; k < 3; k++)
            if (wok[k]) (&s_w[0][0][0])[tid + k*256] = wgt[wsrc[k] + c0*9];
        __syncthreads();

#pragma unroll
        for (int c = 0; c < 8; c++) {
            float p[4][4];
#pragma unroll
            for (int r = 0; r < 4; r++)
#pragma unroll
                for (int q = 0; q < 4; q++)
                    p[r][q] = s_in[c][ty*2 + r][tx*2 + q];
#pragma unroll
            for (int ky = 0; ky < 3; ky++) {
#pragma unroll
                for (int kx = 0; kx < 3; kx++) {
                    const float4 wa = *(const float4*)&s_w[c][ky*3+kx][0];
                    const float4 wb = *(const float4*)&s_w[c][ky*3+kx][4];
                    const float w[8] = {wa.x, wa.y, wa.z, wa.w, wb.x, wb.y, wb.z, wb.w};
#pragma unroll
                    for (int py = 0; py < 2; py++) {
#pragma unroll
                        for (int px = 0; px < 2; px++) {
                            const float v = p[py+ky][px+kx];
#pragma unroll
                            for (int o = 0; o < 8; o++)
                                acc[o][py][px] += v * w[o];
                        }
                    }
                }
            }
        }
    }

#pragma unroll
    for (int o = 0; o < 8; o++) {
        const float bv = __ldg(&bias[co0 + o]);
#pragma unroll
        for (int py = 0; py < 2; py++) {
            const int y = y0 + ty*2 + py;
            const int x = x0 + tx*2;
            float2 v;
            v.x = lrelu(acc[o][py][0] + bv);
            v.y = lrelu(acc[o][py][1] + bv);
            *(float2*)&out[(((b*COUT) + co0 + o)*HH + y)*WW + x] = v;
        }
    }
}

// ---------------- 1x1 redir conv + lrelu -----------------------------------
__global__ __launch_bounds__(256)
void redir_conv(const float* __restrict__ in, const float* __restrict__ wgt,
                const float* __restrict__ bias, float* __restrict__ out)
{
    const int b  = blockIdx.y;
    const int p0 = blockIdx.x * 64;
    const int tid = threadIdx.x;

    __shared__ float s[128*64];
    for (int i = tid; i < 128*64; i += 256) {
        int c = i >> 6, p = i & 63;
        s[c*64 + p] = in[(b*128 + c)*HWW + p0 + p];
    }
    __syncthreads();

    for (int oi = tid; oi < 32*64; oi += 256) {
        const int co = oi >> 6;
        const int p  = oi & 63;
        float sum = bias[co];
#pragma unroll 16
        for (int c = 0; c < 128; c++)
            sum += s[c*64 + p] * __ldg(&wgt[co*128 + c]);
        out[(b*32 + co)*HWW + p0 + p] = lrelu(sum);
    }
}

// ---------------- correlation (patch 21, dil 2) + lrelu (v2) ----------------
// Block = one (b, y) full row. smem: A row [128][192], B row [128][240].
// 144 threads; thread tile = 4 px x 8 dx. Loop dy = 0..20, restage B row.
#define SB_STRIDE 240
__global__ __launch_bounds__(144)
void corr_v2(const float* __restrict__ A, const float* __restrict__ Bm,
             float* __restrict__ out)
{
    extern __shared__ float smem[];
    float* sA = smem;                  // [128][192]
    float* sB = smem + 128*192;        // [128][240] (232 used, u -> gx = u-20)

    const int y = blockIdx.x;
    const int b = blockIdx.y;
    const int tid = threadIdx.x;
    const int pxg = tid % 48;          // 48 px groups of 4
    const int dxg = tid / 48;          // 3 dx groups of 8 (last masked to 21)
    const int px0 = pxg * 4;
    const int u0  = px0 + 16*dxg;      // base B index for this tile

    // stage A row (once)
    {
        const float* Ab = A + b*128*HWW + y*WW;
        float4* d = (float4*)sA;
        for (int i = tid; i < 128*48; i += 144) {
            int c = i / 48, v = i % 48;
            d[c*48 + v] = *(const float4*)(Ab + c*HWW + v*4);
        }
    }

    const float inv_c = 1.0f / 128.0f;
    const float* Bb = Bm + b*128*HWW;

    for (int dy = 0; dy < 21; dy++) {
        const int ry = y + dy*2 - 20;
        __syncthreads();
        if (ry < 0 || ry >= HH) {
            const float4 z = {0.f, 0.f, 0.f, 0.f};
            for (int i = tid; i < 21*48; i += 144) {
                int dx = i / 48, v = i % 48;
                *(float4*)&out[((b*441 + dy*21 + dx)*HH + y)*WW + v*4] = z;
            }
            continue;
        }
        // stage B row
        {
            const float* Brow = Bb + ry*WW;
            float4* d = (float4*)sB;
            for (int i = tid; i < 128*60; i += 144) {
                int c = i / 60, v = i % 60;
                int gx = v*4 - 20;
                float4 val;
                if (gx >= 0 && gx + 3 < WW) {
                    val = *(const float4*)(Brow + c*HWW + gx);
                } else {
                    val.x = (gx+0 >= 0 && gx+0 < WW) ? Brow[c*HWW + gx+0] : 0.f;
                    val.y = (gx+1 >= 0 && gx+1 < WW) ? Brow[c*HWW + gx+1] : 0.f;
                    val.z = (gx+2 >= 0 && gx+2 < WW) ? Brow[c*HWW + gx+2] : 0.f;
                    val.w = (gx+3 >= 0 && gx+3 < WW) ? Brow[c*HWW + gx+3] : 0.f;
                }
                d[c*60 + v] = val;
            }
        }
        __syncthreads();

        float acc[8][4];
#pragma unroll
        for (int d = 0; d < 8; d++)
#pragma unroll
            for (int p = 0; p < 4; p++) acc[d][p] = 0.f;

        const float* pa = sA + px0;
        const float* pb = sB + u0;
#pragma unroll 2
        for (int c = 0; c < 128; c++) {
            const float4 av = *(const float4*)(pa + c*192);
            const float a[4] = {av.x, av.y, av.z, av.w};
            const float4 b0 = *(const float4*)(pb + c*SB_STRIDE + 0);
            const float4 b1 = *(const float4*)(pb + c*SB_STRIDE + 4);
            const float4 b2 = *(const float4*)(pb + c*SB_STRIDE + 8);
            const float4 b3 = *(const float4*)(pb + c*SB_STRIDE + 12);
            const float4 b4 = *(const float4*)(pb + c*SB_STRIDE + 16);
            const float bv[20] = {b0.x,b0.y,b0.z,b0.w, b1.x,b1.y,b1.z,b1.w,
                                  b2.x,b2.y,b2.z,b2.w, b3.x,b3.y,b3.z,b3.w,
                                  b4.x,b4.y,b4.z,b4.w};
#pragma unroll
            for (int d = 0; d < 8; d++)
#pragma unroll
                for (int p = 0; p < 4; p++)
                    acc[d][p] += a[p] * bv[2*d + p];
        }

#pragma unroll
        for (int d = 0; d < 8; d++) {
            const int dx = dxg*8 + d;
            if (dx < 21) {
                float4 v;
                v.x = lrelu(acc[d][0] * inv_c);
                v.y = lrelu(acc[d][1] * inv_c);
                v.z = lrelu(acc[d][2] * inv_c);
                v.w = lrelu(acc[d][3] * inv_c);
                *(float4*)&out[((b*441 + dy*21 + dx)*HH + y)*WW + px0] = v;
            }
        }
    }
}

// ---------------- final 3x3 conv over concat(redir(32), corr(441)) ----------
// Block 16x16 threads, tile 32x32, per thread 2x2 px x 2 co.
__global__ __launch_bounds__(256)
void final_conv_v2(const float* __restrict__ redir, const float* __restrict__ corr,
                   const float* __restrict__ wgt, float* __restrict__ out)
{
    const int x0 = blockIdx.x * 32;
    const int y0 = blockIdx.y * 32;
    const int b  = blockIdx.z;
    const int tx = threadIdx.x, ty = threadIdx.y;
    const int tid = ty*16 + tx;

    __shared__ float s[8][34][36];
    __shared__ float sw[8][9][2];

    // staging slots
    int  soff[5];  int spat[5];
    bool inb[5];   bool wr[5];
#pragma unroll
    for (int k = 0; k < 5; k++) {
        int i = tid + k*256;
        bool ok = (i < 34*34);
        int ii = ok ? i : 0;
        int ly = ii / 34, lx = ii % 34;
        int gy = y0 + ly - 1, gx = x0 + lx - 1;
        bool v = ok && (gy >= 0) && (gy < HH) && (gx >= 0) && (gx < WW);
        soff[k] = ly*36 + lx;
        spat[k] = v ? gy*WW + gx : 0;
        inb[k]  = v;
        wr[k]   = ok;
    }

    float acc[2][2][2];
#pragma unroll
    for (int o = 0; o < 2; o++)
#pragma unroll
        for (int py = 0; py < 2; py++)
#pragma unroll
            for (int px = 0; px < 2; px++) acc[o][py][px] = 0.f;

    for (int c0 = 0; c0 < 473; c0 += 8) {
        const int cn = (473 - c0) < 8 ? (473 - c0) : 8;
        const float* base = (c0 < 32) ? (redir + (b*32 + c0)*HWW)
                                      : (corr + (b*441 + (c0 - 32))*HWW);
        __syncthreads();
#pragma unroll
        for (int k = 0; k < 5; k++) {
            if (wr[k]) {
                float* sp = &s[0][0][0] + soff[k];
                if (inb[k]) {
                    const float* p = base + spat[k];
                    for (int c = 0; c < cn; c++) sp[c*(34*36)] = p[c*HWW];
                    for (int c = cn; c < 8; c++) sp[c*(34*36)] = 0.f;
                } else {
#pragma unroll
                    for (int c = 0; c < 8; c++) sp[c*(34*36)] = 0.f;
                }
            }
        }
        // weights: sw[c][k][o]
        for (int i = tid; i < cn*18; i += 256) {
            int c = i / 18, r = i % 18;
            int kk = r / 2, o = r % 2;
            sw[c][kk][o] = wgt[(o*473 + c0 + c)*9 + kk];
        }
        for (int i = tid + cn*18; i < 8*18; i += 256) {
            int c = i / 18, r = i % 18;
            sw[c][r/2][r%2] = 0.f;
        }
        __syncthreads();

#pragma unroll
        for (int c = 0; c < 8; c++) {
            float p[4][4];
#pragma unroll
            for (int r = 0; r < 4; r++)
#pragma unroll
                for (int q = 0; q < 4; q++)
                    p[r][q] = s[c][ty*2 + r][tx*2 + q];
#pragma unroll
            for (int ky = 0; ky < 3; ky++) {
#pragma unroll
                for (int kx = 0; kx < 3; kx++) {
                    const float w0 = sw[c][ky*3+kx][0];
                    const float w1 = sw[c][ky*3+kx][1];
#pragma unroll
                    for (int py = 0; py < 2; py++) {
#pragma unroll
                        for (int px = 0; px < 2; px++) {
                            const float v = p[py+ky][px+kx];
                            acc[0][py][px] += v * w0;
                            acc[1][py][px] += v * w1;
                        }
                    }
                }
            }
        }
    }

#pragma unroll
    for (int o = 0; o < 2; o++) {
#pragma unroll
        for (int py = 0; py < 2; py++) {
            const int y = y0 + ty*2 + py;
            const int x = x0 + tx*2;
            float2 v;
            v.x = acc[o][py][0];
            v.y = acc[o][py][1];
            *(float2*)&out[((b*2 + o)*HH + y)*WW + x] = v;
        }
    }
}

// ---------------- launch -----------------------------------------------------
extern "C" void kernel_launch(void* const* d_in, const int* in_sizes, int n_in,
                              void* d_out, int out_size)
{
    const float* pred    = (const float*)d_in[0];
    const float* ref     = (const float*)d_in[1];
    const float* conv1_w = (const float*)d_in[2];
    const float* conv1_b = (const float*)d_in[3];
    const float* conv2_w = (const float*)d_in[4];
    const float* conv2_b = (const float*)d_in[5];
    const float* redir_w = (const float*)d_in[6];
    const float* redir_b = (const float*)d_in[7];
    const float* pred_w  = (const float*)d_in[8];
    float* out = (float*)d_out;

    float *c1a, *c1b, *c2a, *c2b, *rdr, *cor;
    cudaGetSymbolAddress((void**)&c1a, g_c1a);
    cudaGetSymbolAddress((void**)&c1b, g_c1b);
    cudaGetSymbolAddress((void**)&c2a, g_c2a);
    cudaGetSymbolAddress((void**)&c2b, g_c2b);
    cudaGetSymbolAddress((void**)&rdr, g_redir);
    cudaGetSymbolAddress((void**)&cor, g_corr);

    // conv1 (64->64) on pred and ref
    {
        dim3 grid(WW/32, HH/32, BB * (64/8));
        dim3 blk(16, 16);
        conv3x3_v2<64,64><<<grid, blk>>>(pred, conv1_w, conv1_b, c1a);
        conv3x3_v2<64,64><<<grid, blk>>>(ref,  conv1_w, conv1_b, c1b);
    }
    // conv2 (64->128)
    {
        dim3 grid(WW/32, HH/32, BB * (128/8));
        dim3 blk(16, 16);
        conv3x3_v2<64,128><<<grid, blk>>>(c1a, conv2_w, conv2_b, c2a);
        conv3x3_v2<64,128><<<grid, blk>>>(c1b, conv2_w, conv2_b, c2b);
    }
    // redir 1x1 (128->32)
    {
        dim3 grid(HWW/64, BB);
        redir_conv<<<grid, 256>>>(c2a, redir_w, redir_b, rdr);
    }
    // correlation
    {
        const int smem_bytes = (128*192 + 128*SB_STRIDE) * (int)sizeof(float); // 221184
        cudaFuncSetAttribute(corr_v2, cudaFuncAttributeMaxDynamicSharedMemorySize, smem_bytes);
        dim3 grid(HH, BB);
        corr_v2<<<grid, 144, smem_bytes>>>(c2a, c2b, cor);
    }
    // final conv (473->2)
    {
        dim3 grid(WW/32, HH/32, BB);
        dim3 blk(16, 16);
        final_conv_v2<<<grid, blk>>>(rdr, cor, pred_w, out);
    }
}

// round 4
// speedup vs baseline: 2.0693x; 1.2251x over previous
#include <cuda_runtime.h>
#include <cstdint>

#define HH 192
#define WW 192
#define BB 4
#define HWW (HH*WW)

// ---------------- scratch buffers (device globals; no allocation) ----------
__device__ float g_c1a[BB*64*HWW];
__device__ float g_c1b[BB*64*HWW];
__device__ float g_c2a[BB*128*HWW];
__device__ float g_c2b[BB*128*HWW];
__device__ float g_redir[BB*32*HWW];
__device__ float g_corr[BB*441*HWW];

__device__ __forceinline__ float lrelu(float x) { return x >= 0.f ? x : 0.1f * x; }

__device__ __forceinline__ void cp_async4(uint32_t dst, const void* src, bool p) {
    asm volatile("cp.async.ca.shared.global [%0], [%1], 4, %2;"
                 :: "r"(dst), "l"(src), "r"(p ? 4 : 0));
}
__device__ __forceinline__ void cp_commit() {
    asm volatile("cp.async.commit_group;");
}
__device__ __forceinline__ void cp_wait0() {
    asm volatile("cp.async.wait_group 0;");
}

// ---------------- 3x3 conv + bias + leaky relu (v3: cp.async dbl-buffer) ----
// Block 16x16 threads. Output tile: 32x32 px x 8 output channels.
// Per thread: 2x2 pixels x 8 co. Staging via cp.async into 2 smem buffers.
#define SIN_SZ (8*34*36)     // floats per input buffer
#define SW_SZ  (8*9*8)       // floats per weight buffer (576)

template<int CIN, int COUT>
__global__ __launch_bounds__(256)
void conv3x3_v3(const float* __restrict__ in, const float* __restrict__ wgt,
                const float* __restrict__ bias, float* __restrict__ out)
{
    extern __shared__ float smem[];
    const int x0 = blockIdx.x * 32;
    const int y0 = blockIdx.y * 32;
    const int bz = blockIdx.z;
    const int b   = bz / (COUT/8);
    const int co0 = (bz % (COUT/8)) * 8;
    const int tx = threadIdx.x, ty = threadIdx.y;
    const int tid = ty*16 + tx;

    uint32_t smem_u32 = (uint32_t)__cvta_generic_to_shared(smem);

    // --- precompute input staging slots (1156 positions, <=5 per thread) ---
    int  soff[5];  int goff[5];
    bool inb[5];   bool wr[5];
#pragma unroll
    for (int k = 0; k < 5; k++) {
        int i = tid + k*256;
        bool ok = (i < 34*34);
        int ii = ok ? i : 0;
        int ly = ii / 34, lx = ii % 34;
        int gy = y0 + ly - 1, gx = x0 + lx - 1;
        bool v = ok && (gy >= 0) && (gy < HH) && (gx >= 0) && (gx < WW);
        soff[k] = ly*36 + lx;
        goff[k] = v ? ((b*CIN)*HH + gy)*WW + gx : 0;
        inb[k]  = v;
        wr[k]   = ok;
    }
    // --- precompute weight staging slots (576 elements, <=3 per thread) ---
    int wsrc[3]; bool wok[3];
#pragma unroll
    for (int k = 0; k < 3; k++) {
        int i = tid + k*256;
        bool ok = (i < 576);
        int ii = ok ? i : 0;
        int c = ii / 72, r = ii % 72;
        int kk = r / 8, o = r % 8;
        wsrc[k] = ((co0 + o)*CIN + c)*9 + kk;   // + c0*9 later
        wok[k]  = ok;
    }

    auto stage = [&](int buf, int c0) {
        uint32_t in_dst = smem_u32 + buf*(SIN_SZ*4);
#pragma unroll
        for (int k = 0; k < 5; k++) {
            if (wr[k]) {
                const float* src = in + goff[k] + c0*HWW;
                uint32_t d = in_dst + soff[k]*4;
#pragma unroll
                for (int c = 0; c < 8; c++)
                    cp_async4(d + c*(34*36*4), src + c*HWW, inb[k]);
            }
        }
        uint32_t w_dst = smem_u32 + (2*SIN_SZ + buf*SW_SZ)*4;
#pragma unroll
        for (int k = 0; k < 3; k++)
            if (wok[k]) cp_async4(w_dst + (tid + k*256)*4, wgt + wsrc[k] + c0*9, true);
        cp_commit();
    };

    float acc[8][2][2];
#pragma unroll
    for (int o = 0; o < 8; o++)
#pragma unroll
        for (int py = 0; py < 2; py++)
#pragma unroll
            for (int px = 0; px < 2; px++) acc[o][py][px] = 0.f;

    stage(0, 0);

    const int NCH = CIN/8;
    for (int ci = 0; ci < NCH; ci++) {
        cp_wait0();
        __syncthreads();
        if (ci + 1 < NCH) stage((ci+1) & 1, (ci+1)*8);

        const float* s_in = smem + (ci & 1)*SIN_SZ;
        const float* s_w  = smem + 2*SIN_SZ + (ci & 1)*SW_SZ;

#pragma unroll
        for (int c = 0; c < 8; c++) {
            float p[4][4];
#pragma unroll
            for (int r = 0; r < 4; r++)
#pragma unroll
                for (int q = 0; q < 4; q++)
                    p[r][q] = s_in[c*(34*36) + (ty*2 + r)*36 + tx*2 + q];
#pragma unroll
            for (int ky = 0; ky < 3; ky++) {
#pragma unroll
                for (int kx = 0; kx < 3; kx++) {
                    const float4 wa = *(const float4*)&s_w[(c*9 + ky*3+kx)*8 + 0];
                    const float4 wb = *(const float4*)&s_w[(c*9 + ky*3+kx)*8 + 4];
                    const float w[8] = {wa.x, wa.y, wa.z, wa.w, wb.x, wb.y, wb.z, wb.w};
#pragma unroll
                    for (int py = 0; py < 2; py++) {
#pragma unroll
                        for (int px = 0; px < 2; px++) {
                            const float v = p[py+ky][px+kx];
#pragma unroll
                            for (int o = 0; o < 8; o++)
                                acc[o][py][px] += v * w[o];
                        }
                    }
                }
            }
        }
    }

#pragma unroll
    for (int o = 0; o < 8; o++) {
        const float bv = __ldg(&bias[co0 + o]);
#pragma unroll
        for (int py = 0; py < 2; py++) {
            const int y = y0 + ty*2 + py;
            const int x = x0 + tx*2;
            float2 v;
            v.x = lrelu(acc[o][py][0] + bv);
            v.y = lrelu(acc[o][py][1] + bv);
            *(float2*)&out[(((b*COUT) + co0 + o)*HH + y)*WW + x] = v;
        }
    }
}

// ---------------- 1x1 redir conv + lrelu -----------------------------------
__global__ __launch_bounds__(256)
void redir_conv(const float* __restrict__ in, const float* __restrict__ wgt,
                const float* __restrict__ bias, float* __restrict__ out)
{
    const int b  = blockIdx.y;
    const int p0 = blockIdx.x * 64;
    const int tid = threadIdx.x;

    __shared__ float s[128*64];
    for (int i = tid; i < 128*64; i += 256) {
        int c = i >> 6, p = i & 63;
        s[c*64 + p] = in[(b*128 + c)*HWW + p0 + p];
    }
    __syncthreads();

    for (int oi = tid; oi < 32*64; oi += 256) {
        const int co = oi >> 6;
        const int p  = oi & 63;
        float sum = bias[co];
#pragma unroll 16
        for (int c = 0; c < 128; c++)
            sum += s[c*64 + p] * __ldg(&wgt[co*128 + c]);
        out[(b*32 + co)*HWW + p0 + p] = lrelu(sum);
    }
}

// ---------------- correlation (patch 21, dil 2) + lrelu (v3) ----------------
// Block = one (b, y) full row, 576 threads (18 warps).
// Warp: dxg = warp%3 (8 dx), pxblk = warp/3 (32 px). Lane: cq = lane>>3
// (channel quarter), sub = lane&7 (4 px). Each lane: acc[8dx][4px] over its
// 32 channels; 4 partial sums combined with shfl_down (stride 16 then 8).
#define SB_STRIDE 240
__global__ __launch_bounds__(576)
void corr_v3(const float* __restrict__ A, const float* __restrict__ Bm,
             float* __restrict__ out)
{
    extern __shared__ float smem[];
    float* sA = smem;                  // [128][192]
    float* sB = smem + 128*192;        // [128][240] (u -> gx = u-20)

    const int y = blockIdx.x;
    const int b = blockIdx.y;
    const int tid = threadIdx.x;
    const int warp = tid >> 5;
    const int lane = tid & 31;
    const int cq  = lane >> 3;         // channel quarter 0..3
    const int sub = lane & 7;          // px sub-tile 0..7
    const int dxg   = warp % 3;        // 3 dx groups of 8
    const int pxblk = warp / 3;        // 6 blocks of 32 px
    const int px0 = pxblk*32 + sub*4;
    const int u0  = px0 + 16*dxg;
    const int cbase = cq*32;

    // stage A row (once): 128 x 48 float4
    {
        const float* Ab = A + (b*128)*HWW + y*WW;
        float4* d = (float4*)sA;
        for (int i = tid; i < 128*48; i += 576) {
            int c = i / 48, v = i % 48;
            d[c*48 + v] = *(const float4*)(Ab + c*HWW + v*4);
        }
    }

    const float inv_c = 1.0f / 128.0f;
    const float* Bb = Bm + (b*128)*HWW;

    for (int dy = 0; dy < 21; dy++) {
        const int ry = y + dy*2 - 20;
        __syncthreads();
        if (ry < 0 || ry >= HH) {
            const float4 z = {0.f, 0.f, 0.f, 0.f};
            for (int i = tid; i < 21*48; i += 576) {
                int dx = i / 48, v = i % 48;
                *(float4*)&out[((b*441 + dy*21 + dx)*HH + y)*WW + v*4] = z;
            }
            continue;
        }
        // stage B row: 128 x 60 float4
        {
            const float* Brow = Bb + ry*WW;
            float4* d = (float4*)sB;
            for (int i = tid; i < 128*60; i += 576) {
                int c = i / 60, v = i % 60;
                int gx = v*4 - 20;
                float4 val;
                if (gx >= 0 && gx + 3 < WW) {
                    val = *(const float4*)(Brow + c*HWW + gx);
                } else {
                    val.x = (gx+0 >= 0 && gx+0 < WW) ? Brow[c*HWW + gx+0] : 0.f;
                    val.y = (gx+1 >= 0 && gx+1 < WW) ? Brow[c*HWW + gx+1] : 0.f;
                    val.z = (gx+2 >= 0 && gx+2 < WW) ? Brow[c*HWW + gx+2] : 0.f;
                    val.w = (gx+3 >= 0 && gx+3 < WW) ? Brow[c*HWW + gx+3] : 0.f;
                }
                d[c*60 + v] = val;
            }
        }
        __syncthreads();

        float acc[8][4];
#pragma unroll
        for (int d = 0; d < 8; d++)
#pragma unroll
            for (int p = 0; p < 4; p++) acc[d][p] = 0.f;

        const float* pa = sA + px0 + cbase*192;
        const float* pb = sB + u0  + cbase*SB_STRIDE;
#pragma unroll 4
        for (int cc = 0; cc < 32; cc++) {
            const float4 av = *(const float4*)(pa + cc*192);
            const float a[4] = {av.x, av.y, av.z, av.w};
            const float4 b0 = *(const float4*)(pb + cc*SB_STRIDE + 0);
            const float4 b1 = *(const float4*)(pb + cc*SB_STRIDE + 4);
            const float4 b2 = *(const float4*)(pb + cc*SB_STRIDE + 8);
            const float4 b3 = *(const float4*)(pb + cc*SB_STRIDE + 12);
            const float4 b4 = *(const float4*)(pb + cc*SB_STRIDE + 16);
            const float bv[20] = {b0.x,b0.y,b0.z,b0.w, b1.x,b1.y,b1.z,b1.w,
                                  b2.x,b2.y,b2.z,b2.w, b3.x,b3.y,b3.z,b3.w,
                                  b4.x,b4.y,b4.z,b4.w};
#pragma unroll
            for (int d = 0; d < 8; d++)
#pragma unroll
                for (int p = 0; p < 4; p++)
                    acc[d][p] += a[p] * bv[2*d + p];
        }

        // combine the 4 channel-quarter partials (lanes l, l+8, l+16, l+24)
#pragma unroll
        for (int d = 0; d < 8; d++)
#pragma unroll
            for (int p = 0; p < 4; p++) {
                float v = acc[d][p];
                v += __shfl_down_sync(0xffffffffu, v, 16);
                v += __shfl_down_sync(0xffffffffu, v, 8);
                acc[d][p] = v;
            }

        if (cq == 0) {
#pragma unroll
            for (int d = 0; d < 8; d++) {
                const int dx = dxg*8 + d;
                if (dx < 21) {
                    float4 v;
                    v.x = lrelu(acc[d][0] * inv_c);
                    v.y = lrelu(acc[d][1] * inv_c);
                    v.z = lrelu(acc[d][2] * inv_c);
                    v.w = lrelu(acc[d][3] * inv_c);
                    *(float4*)&out[((b*441 + dy*21 + dx)*HH + y)*WW + px0] = v;
                }
            }
        }
    }
}

// ---------------- final 3x3 conv over concat(redir(32), corr(441)) ----------
__global__ __launch_bounds__(256)
void final_conv_v2(const float* __restrict__ redir, const float* __restrict__ corr,
                   const float* __restrict__ wgt, float* __restrict__ out)
{
    const int x0 = blockIdx.x * 32;
    const int y0 = blockIdx.y * 32;
    const int b  = blockIdx.z;
    const int tx = threadIdx.x, ty = threadIdx.y;
    const int tid = ty*16 + tx;

    __shared__ float s[8][34][36];
    __shared__ float sw[8][9][2];

    int  soff[5];  int spat[5];
    bool inb[5];   bool wr[5];
#pragma unroll
    for (int k = 0; k < 5; k++) {
        int i = tid + k*256;
        bool ok = (i < 34*34);
        int ii = ok ? i : 0;
        int ly = ii / 34, lx = ii % 34;
        int gy = y0 + ly - 1, gx = x0 + lx - 1;
        bool v = ok && (gy >= 0) && (gy < HH) && (gx >= 0) && (gx < WW);
        soff[k] = ly*36 + lx;
        spat[k] = v ? gy*WW + gx : 0;
        inb[k]  = v;
        wr[k]   = ok;
    }

    float acc[2][2][2];
#pragma unroll
    for (int o = 0; o < 2; o++)
#pragma unroll
        for (int py = 0; py < 2; py++)
#pragma unroll
            for (int px = 0; px < 2; px++) acc[o][py][px] = 0.f;

    for (int c0 = 0; c0 < 473; c0 += 8) {
        const int cn = (473 - c0) < 8 ? (473 - c0) : 8;
        const float* base = (c0 < 32) ? (redir + (b*32 + c0)*HWW)
                                      : (corr + (b*441 + (c0 - 32))*HWW);
        __syncthreads();
#pragma unroll
        for (int k = 0; k < 5; k++) {
            if (wr[k]) {
                float* sp = &s[0][0][0] + soff[k];
                if (inb[k]) {
                    const float* p = base + spat[k];
                    for (int c = 0; c < cn; c++) sp[c*(34*36)] = p[c*HWW];
                    for (int c = cn; c < 8; c++) sp[c*(34*36)] = 0.f;
                } else {
#pragma unroll
                    for (int c = 0; c < 8; c++) sp[c*(34*36)] = 0.f;
                }
            }
        }
        for (int i = tid; i < cn*18; i += 256) {
            int c = i / 18, r = i % 18;
            int kk = r / 2, o = r % 2;
            sw[c][kk][o] = wgt[(o*473 + c0 + c)*9 + kk];
        }
        for (int i = tid + cn*18; i < 8*18; i += 256) {
            int c = i / 18, r = i % 18;
            sw[c][r/2][r%2] = 0.f;
        }
        __syncthreads();

#pragma unroll
        for (int c = 0; c < 8; c++) {
            float p[4][4];
#pragma unroll
            for (int r = 0; r < 4; r++)
#pragma unroll
                for (int q = 0; q < 4; q++)
                    p[r][q] = s[c][ty*2 + r][tx*2 + q];
#pragma unroll
            for (int ky = 0; ky < 3; ky++) {
#pragma unroll
                for (int kx = 0; kx < 3; kx++) {
                    const float w0 = sw[c][ky*3+kx][0];
                    const float w1 = sw[c][ky*3+kx][1];
#pragma unroll
                    for (int py = 0; py < 2; py++) {
#pragma unroll
                        for (int px = 0; px < 2; px++) {
                            const float v = p[py+ky][px+kx];
                            acc[0][py][px] += v * w0;
                            acc[1][py][px] += v * w1;
                        }
                    }
                }
            }
        }
    }

#pragma unroll
    for (int o = 0; o < 2; o++) {
#pragma unroll
        for (int py = 0; py < 2; py++) {
            const int y = y0 + ty*2 + py;
            const int x = x0 + tx*2;
            float2 v;
            v.x = acc[o][py][0];
            v.y = acc[o][py][1];
            *(float2*)&out[((b*2 + o)*HH + y)*WW + x] = v;
        }
    }
}

// ---------------- launch -----------------------------------------------------
extern "C" void kernel_launch(void* const* d_in, const int* in_sizes, int n_in,
                              void* d_out, int out_size)
{
    const float* pred    = (const float*)d_in[0];
    const float* ref     = (const float*)d_in[1];
    const float* conv1_w = (const float*)d_in[2];
    const float* conv1_b = (const float*)d_in[3];
    const float* conv2_w = (const float*)d_in[4];
    const float* conv2_b = (const float*)d_in[5];
    const float* redir_w = (const float*)d_in[6];
    const float* redir_b = (const float*)d_in[7];
    const float* pred_w  = (const float*)d_in[8];
    float* out = (float*)d_out;

    float *c1a, *c1b, *c2a, *c2b, *rdr, *cor;
    cudaGetSymbolAddress((void**)&c1a, g_c1a);
    cudaGetSymbolAddress((void**)&c1b, g_c1b);
    cudaGetSymbolAddress((void**)&c2a, g_c2a);
    cudaGetSymbolAddress((void**)&c2b, g_c2b);
    cudaGetSymbolAddress((void**)&rdr, g_redir);
    cudaGetSymbolAddress((void**)&cor, g_corr);

    const int conv_smem = (2*SIN_SZ + 2*SW_SZ) * (int)sizeof(float); // 82944
    cudaFuncSetAttribute(conv3x3_v3<64,64>,  cudaFuncAttributeMaxDynamicSharedMemorySize, conv_smem);
    cudaFuncSetAttribute(conv3x3_v3<64,128>, cudaFuncAttributeMaxDynamicSharedMemorySize, conv_smem);

    // conv1 (64->64) on pred and ref
    {
        dim3 grid(WW/32, HH/32, BB * (64/8));
        dim3 blk(16, 16);
        conv3x3_v3<64,64><<<grid, blk, conv_smem>>>(pred, conv1_w, conv1_b, c1a);
        conv3x3_v3<64,64><<<grid, blk, conv_smem>>>(ref,  conv1_w, conv1_b, c1b);
    }
    // conv2 (64->128)
    {
        dim3 grid(WW/32, HH/32, BB * (128/8));
        dim3 blk(16, 16);
        conv3x3_v3<64,128><<<grid, blk, conv_smem>>>(c1a, conv2_w, conv2_b, c2a);
        conv3x3_v3<64,128><<<grid, blk, conv_smem>>>(c1b, conv2_w, conv2_b, c2b);
    }
    // redir 1x1 (128->32)
    {
        dim3 grid(HWW/64, BB);
        redir_conv<<<grid, 256>>>(c2a, redir_w, redir_b, rdr);
    }
    // correlation
    {
        const int smem_bytes = (128*192 + 128*SB_STRIDE) * (int)sizeof(float); // 221184
        cudaFuncSetAttribute(corr_v3, cudaFuncAttributeMaxDynamicSharedMemorySize, smem_bytes);
        dim3 grid(HH, BB);
        corr_v3<<<grid, 576, smem_bytes>>>(c2a, c2b, cor);
    }
    // final conv (473->2)
    {
        dim3 grid(WW/32, HH/32, BB);
        dim3 blk(16, 16);
        final_conv_v2<<<grid, blk>>>(rdr, cor, pred_w, out);
    }
}

// round 5
// speedup vs baseline: 2.1367x; 1.0326x over previous
#include <cuda_runtime.h>
#include <cstdint>

#define HH 192
#define WW 192
#define BB 4
#define HWW (HH*WW)

// ---------------- scratch buffers (device globals; no allocation) ----------
__device__ float g_c1a[BB*64*HWW];
__device__ float g_c1b[BB*64*HWW];
__device__ float g_c2a[BB*128*HWW];
__device__ float g_c2b[BB*128*HWW];
__device__ float g_redir[BB*32*HWW];
__device__ float g_corr[BB*441*HWW];

__device__ __forceinline__ float lrelu(float x) { return x >= 0.f ? x : 0.1f * x; }

__device__ __forceinline__ void cp_async4(uint32_t dst, const void* src, bool p) {
    asm volatile("cp.async.ca.shared.global [%0], [%1], 4, %2;"
                 :: "r"(dst), "l"(src), "r"(p ? 4 : 0));
}
__device__ __forceinline__ void cp_commit() {
    asm volatile("cp.async.commit_group;");
}
__device__ __forceinline__ void cp_wait0() {
    asm volatile("cp.async.wait_group 0;");
}

// ---------------- 3x3 conv + bias + leaky relu (v4) -------------------------
// Block 16x16 threads, 3 blocks/SM. Output tile: 32x32 px x 8 co.
// Weights for the whole co-group pre-staged once (CIN*72 floats).
// Inputs double-buffered via cp.async in 4-channel chunks.
#define SIN4 (4*34*36)       // floats per input buffer (4896)

template<int CIN, int COUT>
__global__ __launch_bounds__(256, 3)
void conv3x3_v4(const float* __restrict__ in, const float* __restrict__ wgt,
                const float* __restrict__ bias, float* __restrict__ out)
{
    extern __shared__ float smem[];   // [2*SIN4 inputs][CIN*72 weights]
    float* s_w = smem + 2*SIN4;

    const int x0 = blockIdx.x * 32;
    const int y0 = blockIdx.y * 32;
    const int bz = blockIdx.z;
    const int b   = bz / (COUT/8);
    const int co0 = (bz % (COUT/8)) * 8;
    const int tx = threadIdx.x, ty = threadIdx.y;
    const int tid = ty*16 + tx;

    uint32_t smem_u32 = (uint32_t)__cvta_generic_to_shared(smem);

    // --- precompute input staging slots (1156 positions, <=5 per thread) ---
    int  soff[5];  int goff[5];
    bool inb[5];   bool wr[5];
#pragma unroll
    for (int k = 0; k < 5; k++) {
        int i = tid + k*256;
        bool ok = (i < 34*34);
        int ii = ok ? i : 0;
        int ly = ii / 34, lx = ii % 34;
        int gy = y0 + ly - 1, gx = x0 + lx - 1;
        bool v = ok && (gy >= 0) && (gy < HH) && (gx >= 0) && (gx < WW);
        soff[k] = ly*36 + lx;
        goff[k] = v ? ((b*CIN)*HH + gy)*WW + gx : 0;
        inb[k]  = v;
        wr[k]   = ok;
    }

    auto stage = [&](int buf, int c0) {
        uint32_t in_dst = smem_u32 + buf*(SIN4*4);
#pragma unroll
        for (int k = 0; k < 5; k++) {
            if (wr[k]) {
                const float* src = in + goff[k] + c0*HWW;
                uint32_t d = in_dst + soff[k]*4;
#pragma unroll
                for (int c = 0; c < 4; c++)
                    cp_async4(d + c*(34*36*4), src + c*HWW, inb[k]);
            }
        }
        cp_commit();
    };

    // kick off first input chunk
    stage(0, 0);

    // pre-stage ALL weights for this co-group: s_w[c][k][o], c<CIN,k<9,o<8
    for (int i = tid; i < CIN*72; i += 256) {
        int c = i / 72, r = i % 72;
        int k = r / 8,  o = r % 8;
        s_w[i] = wgt[((co0 + o)*CIN + c)*9 + k];
    }

    float acc[8][2][2];
#pragma unroll
    for (int o = 0; o < 8; o++)
#pragma unroll
        for (int py = 0; py < 2; py++)
#pragma unroll
            for (int px = 0; px < 2; px++) acc[o][py][px] = 0.f;

    const int NCH = CIN/4;
    for (int ci = 0; ci < NCH; ci++) {
        cp_wait0();
        __syncthreads();
        if (ci + 1 < NCH) stage((ci+1) & 1, (ci+1)*4);

        const float* s_in = smem + (ci & 1)*SIN4;
        const float* wbase = s_w + ci*4*72;

#pragma unroll
        for (int c = 0; c < 4; c++) {
            float p[4][4];
#pragma unroll
            for (int r = 0; r < 4; r++)
#pragma unroll
                for (int q = 0; q < 4; q++)
                    p[r][q] = s_in[c*(34*36) + (ty*2 + r)*36 + tx*2 + q];
#pragma unroll
            for (int ky = 0; ky < 3; ky++) {
#pragma unroll
                for (int kx = 0; kx < 3; kx++) {
                    const float4 wa = *(const float4*)&wbase[c*72 + (ky*3+kx)*8 + 0];
                    const float4 wb = *(const float4*)&wbase[c*72 + (ky*3+kx)*8 + 4];
                    const float w[8] = {wa.x, wa.y, wa.z, wa.w, wb.x, wb.y, wb.z, wb.w};
#pragma unroll
                    for (int py = 0; py < 2; py++) {
#pragma unroll
                        for (int px = 0; px < 2; px++) {
                            const float v = p[py+ky][px+kx];
#pragma unroll
                            for (int o = 0; o < 8; o++)
                                acc[o][py][px] += v * w[o];
                        }
                    }
                }
            }
        }
    }

#pragma unroll
    for (int o = 0; o < 8; o++) {
        const float bv = __ldg(&bias[co0 + o]);
#pragma unroll
        for (int py = 0; py < 2; py++) {
            const int y = y0 + ty*2 + py;
            const int x = x0 + tx*2;
            float2 v;
            v.x = lrelu(acc[o][py][0] + bv);
            v.y = lrelu(acc[o][py][1] + bv);
            *(float2*)&out[(((b*COUT) + co0 + o)*HH + y)*WW + x] = v;
        }
    }
}

// ---------------- 1x1 redir conv + lrelu -----------------------------------
__global__ __launch_bounds__(256)
void redir_conv(const float* __restrict__ in, const float* __restrict__ wgt,
                const float* __restrict__ bias, float* __restrict__ out)
{
    const int b  = blockIdx.y;
    const int p0 = blockIdx.x * 64;
    const int tid = threadIdx.x;

    __shared__ float s[128*64];
    for (int i = tid; i < 128*64; i += 256) {
        int c = i >> 6, p = i & 63;
        s[c*64 + p] = in[(b*128 + c)*HWW + p0 + p];
    }
    __syncthreads();

    for (int oi = tid; oi < 32*64; oi += 256) {
        const int co = oi >> 6;
        const int p  = oi & 63;
        float sum = bias[co];
#pragma unroll 16
        for (int c = 0; c < 128; c++)
            sum += s[c*64 + p] * __ldg(&wgt[co*128 + c]);
        out[(b*32 + co)*HWW + p0 + p] = lrelu(sum);
    }
}

// ---------------- correlation (patch 21, dil 2) + lrelu (v4) ----------------
// Block = one (b, y) row, 288 threads (9 warps).
// Warp: dxg = warp%3 (8/8/5 dx), pxblk = warp/3 (64 px). Lane: cq = lane>>3
// (channel quarter, 32 ch each), sub = lane&7 (8 px). Lane tile: 8 px x 8 dx.
// smem float4-swizzled (v ^= (v>>3)&1) so stride-2-float4 phase reads are
// bank-conflict-free. Partials combined with shfl_down 16, 8.
#define SBW 60     // float4 per B row (240 floats)
#define SAW 48     // float4 per A row (192 floats)
__device__ __forceinline__ int SWZ(int v) { return v ^ ((v >> 3) & 1); }

__global__ __launch_bounds__(288)
void corr_v4(const float* __restrict__ A, const float* __restrict__ Bm,
             float* __restrict__ out)
{
    extern __shared__ float smem[];
    float4* sA4 = (float4*)smem;               // [128][SAW]
    float4* sB4 = (float4*)(smem + 128*192);   // [128][SBW] (u -> gx = u-20)

    const int y = blockIdx.x;
    const int b = blockIdx.y;
    const int tid = threadIdx.x;
    const int warp = tid >> 5;
    const int lane = tid & 31;
    const int cq  = lane >> 3;         // channel quarter 0..3
    const int sub = lane & 7;          // px sub-tile 0..7
    const int dxg   = warp % 3;        // dx group: 0..7, 8..15, 16..20
    const int pxblk = warp / 3;        // 3 blocks of 64 px
    const int px0 = pxblk*64 + sub*8;
    const int dx0 = dxg*8;
    const int va  = 16*pxblk + 2*sub;          // A float4 base within row
    const int vb  = va + 4*dxg;                // B float4 base within row
    const int cbase = cq*32;

    // stage A row once (swizzled)
    {
        const float* Ab = A + (b*128)*HWW + y*WW;
        for (int i = tid; i < 128*SAW; i += 288) {
            int c = i / SAW, v = i % SAW;
            sA4[c*SAW + SWZ(v)] = *(const float4*)(Ab + c*HWW + v*4);
        }
    }

    const float inv_c = 1.0f / 128.0f;
    const float* Bb = Bm + (b*128)*HWW;

    for (int dy = 0; dy < 21; dy++) {
        const int ry = y + dy*2 - 20;
        __syncthreads();
        if (ry < 0 || ry >= HH) {
            const float4 z = {0.f, 0.f, 0.f, 0.f};
            for (int i = tid; i < 21*48; i += 288) {
                int dx = i / 48, v = i % 48;
                *(float4*)&out[((b*441 + dy*21 + dx)*HH + y)*WW + v*4] = z;
            }
            continue;
        }
        // stage B row (swizzled)
        {
            const float* Brow = Bb + ry*WW;
            for (int i = tid; i < 128*SBW; i += 288) {
                int c = i / SBW, v = i % SBW;
                int gx = v*4 - 20;
                float4 val;
                if (gx >= 0 && gx + 3 < WW) {
                    val = *(const float4*)(Brow + c*HWW + gx);
                } else {
                    val.x = (gx+0 >= 0 && gx+0 < WW) ? Brow[c*HWW + gx+0] : 0.f;
                    val.y = (gx+1 >= 0 && gx+1 < WW) ? Brow[c*HWW + gx+1] : 0.f;
                    val.z = (gx+2 >= 0 && gx+2 < WW) ? Brow[c*HWW + gx+2] : 0.f;
                    val.w = (gx+3 >= 0 && gx+3 < WW) ? Brow[c*HWW + gx+3] : 0.f;
                }
                sB4[c*SBW + SWZ(v)] = val;
            }
        }
        __syncthreads();

        float acc[8][8];
#pragma unroll
        for (int d = 0; d < 8; d++)
#pragma unroll
            for (int p = 0; p < 8; p++) acc[d][p] = 0.f;

        const float4* pa = sA4 + cbase*SAW;
        const float4* pb = sB4 + cbase*SBW;
#pragma unroll 2
        for (int cc = 0; cc < 32; cc++) {
            const float4 a0 = pa[cc*SAW + SWZ(va)];
            const float4 a1 = pa[cc*SAW + SWZ(va+1)];
            const float a[8] = {a0.x,a0.y,a0.z,a0.w, a1.x,a1.y,a1.z,a1.w};
            float bv[24];
#pragma unroll
            for (int j = 0; j < 6; j++) {
                const float4 t = pb[cc*SBW + SWZ(vb + j)];
                bv[4*j+0] = t.x; bv[4*j+1] = t.y; bv[4*j+2] = t.z; bv[4*j+3] = t.w;
            }
#pragma unroll
            for (int d = 0; d < 8; d++)
#pragma unroll
                for (int p = 0; p < 8; p++)
                    acc[d][p] += a[p] * bv[2*d + p];
        }

        // combine 4 channel-quarter partials (lanes l, l+8, l+16, l+24)
#pragma unroll
        for (int d = 0; d < 8; d++)
#pragma unroll
            for (int p = 0; p < 8; p++) {
                float v = acc[d][p];
                v += __shfl_down_sync(0xffffffffu, v, 16);
                v += __shfl_down_sync(0xffffffffu, v, 8);
                acc[d][p] = v;
            }

        if (cq == 0) {
#pragma unroll
            for (int d = 0; d < 8; d++) {
                const int dx = dx0 + d;
                if (dx < 21) {
                    float* o = &out[((b*441 + dy*21 + dx)*HH + y)*WW + px0];
                    float4 v0, v1;
                    v0.x = lrelu(acc[d][0] * inv_c);
                    v0.y = lrelu(acc[d][1] * inv_c);
                    v0.z = lrelu(acc[d][2] * inv_c);
                    v0.w = lrelu(acc[d][3] * inv_c);
                    v1.x = lrelu(acc[d][4] * inv_c);
                    v1.y = lrelu(acc[d][5] * inv_c);
                    v1.z = lrelu(acc[d][6] * inv_c);
                    v1.w = lrelu(acc[d][7] * inv_c);
                    *(float4*)(o)     = v0;
                    *(float4*)(o + 4) = v1;
                }
            }
        }
    }
}

// ---------------- final 3x3 conv over concat(redir(32), corr(441)) ----------
__global__ __launch_bounds__(256)
void final_conv_v2(const float* __restrict__ redir, const float* __restrict__ corr,
                   const float* __restrict__ wgt, float* __restrict__ out)
{
    const int x0 = blockIdx.x * 32;
    const int y0 = blockIdx.y * 32;
    const int b  = blockIdx.z;
    const int tx = threadIdx.x, ty = threadIdx.y;
    const int tid = ty*16 + tx;

    __shared__ float s[8][34][36];
    __shared__ float sw[8][9][2];

    int  soff[5];  int spat[5];
    bool inb[5];   bool wr[5];
#pragma unroll
    for (int k = 0; k < 5; k++) {
        int i = tid + k*256;
        bool ok = (i < 34*34);
        int ii = ok ? i : 0;
        int ly = ii / 34, lx = ii % 34;
        int gy = y0 + ly - 1, gx = x0 + lx - 1;
        bool v = ok && (gy >= 0) && (gy < HH) && (gx >= 0) && (gx < WW);
        soff[k] = ly*36 + lx;
        spat[k] = v ? gy*WW + gx : 0;
        inb[k]  = v;
        wr[k]   = ok;
    }

    float acc[2][2][2];
#pragma unroll
    for (int o = 0; o < 2; o++)
#pragma unroll
        for (int py = 0; py < 2; py++)
#pragma unroll
            for (int px = 0; px < 2; px++) acc[o][py][px] = 0.f;

    for (int c0 = 0; c0 < 473; c0 += 8) {
        const int cn = (473 - c0) < 8 ? (473 - c0) : 8;
        const float* base = (c0 < 32) ? (redir + (b*32 + c0)*HWW)
                                      : (corr + (b*441 + (c0 - 32))*HWW);
        __syncthreads();
#pragma unroll
        for (int k = 0; k < 5; k++) {
            if (wr[k]) {
                float* sp = &s[0][0][0] + soff[k];
                if (inb[k]) {
                    const float* p = base + spat[k];
                    for (int c = 0; c < cn; c++) sp[c*(34*36)] = p[c*HWW];
                    for (int c = cn; c < 8; c++) sp[c*(34*36)] = 0.f;
                } else {
#pragma unroll
                    for (int c = 0; c < 8; c++) sp[c*(34*36)] = 0.f;
                }
            }
        }
        for (int i = tid; i < cn*18; i += 256) {
            int c = i / 18, r = i % 18;
            int kk = r / 2, o = r % 2;
            sw[c][kk][o] = wgt[(o*473 + c0 + c)*9 + kk];
        }
        for (int i = tid + cn*18; i < 8*18; i += 256) {
            int c = i / 18, r = i % 18;
            sw[c][r/2][r%2] = 0.f;
        }
        __syncthreads();

#pragma unroll
        for (int c = 0; c < 8; c++) {
            float p[4][4];
#pragma unroll
            for (int r = 0; r < 4; r++)
#pragma unroll
                for (int q = 0; q < 4; q++)
                    p[r][q] = s[c][ty*2 + r][tx*2 + q];
#pragma unroll
            for (int ky = 0; ky < 3; ky++) {
#pragma unroll
                for (int kx = 0; kx < 3; kx++) {
                    const float w0 = sw[c][ky*3+kx][0];
                    const float w1 = sw[c][ky*3+kx][1];
#pragma unroll
                    for (int py = 0; py < 2; py++) {
#pragma unroll
                        for (int px = 0; px < 2; px++) {
                            const float v = p[py+ky][px+kx];
                            acc[0][py][px] += v * w0;
                            acc[1][py][px] += v * w1;
                        }
                    }
                }
            }
        }
    }

#pragma unroll
    for (int o = 0; o < 2; o++) {
#pragma unroll
        for (int py = 0; py < 2; py++) {
            const int y = y0 + ty*2 + py;
            const int x = x0 + tx*2;
            float2 v;
            v.x = acc[o][py][0];
            v.y = acc[o][py][1];
            *(float2*)&out[((b*2 + o)*HH + y)*WW + x] = v;
        }
    }
}

// ---------------- launch -----------------------------------------------------
extern "C" void kernel_launch(void* const* d_in, const int* in_sizes, int n_in,
                              void* d_out, int out_size)
{
    const float* pred    = (const float*)d_in[0];
    const float* ref     = (const float*)d_in[1];
    const float* conv1_w = (const float*)d_in[2];
    const float* conv1_b = (const float*)d_in[3];
    const float* conv2_w = (const float*)d_in[4];
    const float* conv2_b = (const float*)d_in[5];
    const float* redir_w = (const float*)d_in[6];
    const float* redir_b = (const float*)d_in[7];
    const float* pred_w  = (const float*)d_in[8];
    float* out = (float*)d_out;

    float *c1a, *c1b, *c2a, *c2b, *rdr, *cor;
    cudaGetSymbolAddress((void**)&c1a, g_c1a);
    cudaGetSymbolAddress((void**)&c1b, g_c1b);
    cudaGetSymbolAddress((void**)&c2a, g_c2a);
    cudaGetSymbolAddress((void**)&c2b, g_c2b);
    cudaGetSymbolAddress((void**)&rdr, g_redir);
    cudaGetSymbolAddress((void**)&cor, g_corr);

    const int conv_smem = (2*SIN4 + 64*72) * (int)sizeof(float); // 57600
    cudaFuncSetAttribute(conv3x3_v4<64,64>,  cudaFuncAttributeMaxDynamicSharedMemorySize, conv_smem);
    cudaFuncSetAttribute(conv3x3_v4<64,128>, cudaFuncAttributeMaxDynamicSharedMemorySize, conv_smem);

    // conv1 (64->64) on pred and ref
    {
        dim3 grid(WW/32, HH/32, BB * (64/8));
        dim3 blk(16, 16);
        conv3x3_v4<64,64><<<grid, blk, conv_smem>>>(pred, conv1_w, conv1_b, c1a);
        conv3x3_v4<64,64><<<grid, blk, conv_smem>>>(ref,  conv1_w, conv1_b, c1b);
    }
    // conv2 (64->128)
    {
        dim3 grid(WW/32, HH/32, BB * (128/8));
        dim3 blk(16, 16);
        conv3x3_v4<64,128><<<grid, blk, conv_smem>>>(c1a, conv2_w, conv2_b, c2a);
        conv3x3_v4<64,128><<<grid, blk, conv_smem>>>(c1b, conv2_w, conv2_b, c2b);
    }
    // redir 1x1 (128->32)
    {
        dim3 grid(HWW/64, BB);
        redir_conv<<<grid, 256>>>(c2a, redir_w, redir_b, rdr);
    }
    // correlation
    {
        const int smem_bytes = (128*192 + 128*240) * (int)sizeof(float); // 221184
        cudaFuncSetAttribute(corr_v4, cudaFuncAttributeMaxDynamicSharedMemorySize, smem_bytes);
        dim3 grid(HH, BB);
        corr_v4<<<grid, 288, smem_bytes>>>(c2a, c2b, cor);
    }
    // final conv (473->2)
    {
        dim3 grid(WW/32, HH/32, BB);
        dim3 blk(16, 16);
        final_conv_v2<<<grid, blk>>>(rdr, cor, pred_w, out);
    }
}